// round 6
// baseline (speedup 1.0000x reference)
#include <cuda_runtime.h>

#define BATCH 2
#define C     48
#define C3    144
#define DD    32
#define HD    64
#define WD    64
#define LL    (DD*HD*WD)   /* 131072 */
#define HW    (HD*WD)      /* 4096 */
#define HEADS 6
#define CPH   8

typedef unsigned long long ull;

__device__ __forceinline__ ull pack2(float a, float b) {
    ull r; asm("mov.b64 %0, {%1,%2};" : "=l"(r) : "f"(a), "f"(b)); return r;
}
__device__ __forceinline__ float2 unpack2(ull v) {
    float2 r; asm("mov.b64 {%0,%1}, %2;" : "=f"(r.x), "=f"(r.y) : "l"(v)); return r;
}
__device__ __forceinline__ void fma2(ull& d, ull a, ull b) {
    asm("fma.rn.f32x2 %0, %1, %2, %0;" : "+l"(d) : "l"(a), "l"(b));
}

// ---- scratch ----
__device__ float g_qkv[(size_t)BATCH * C3 * LL];
__device__ float g_dw [(size_t)BATCH * C3 * LL];
__device__ float g_attn[BATCH * HEADS * CPH * CPH];
__device__ float g_weff[BATCH * C * C];

// ---------------------------------------------------------------------------
__global__ void k0_zero() {
    g_attn[threadIdx.x] = 0.0f;
}

// ---------------------------------------------------------------------------
// K1: qkv = W1[144x48] * x[48xL] + b1.  288 threads; W in smem once;
// 8 phases of 32 l. X pre-duplicated {x,x} in smem so the inner loop is pure
// LDS.64 + fma.rn.f32x2 (no packing movs). Thread = 2 l x 8 oc.
// ---------------------------------------------------------------------------
__global__ __launch_bounds__(288) void k1_qkv(const float* __restrict__ x,
                                              const float* __restrict__ w1,
                                              const float* __restrict__ b1) {
    __shared__ float  Wt[48][144];   // [ic][oc]
    __shared__ float2 Xd[48][32];    // [ic][l] duplicated {x,x}

    const int b  = blockIdx.y;
    const size_t l0 = (size_t)blockIdx.x * 256;
    const int tid = threadIdx.x;

    for (int i = tid; i < C3 * C; i += 288) {
        int oc = i / 48, ic = i % 48;
        Wt[ic][oc] = w1[i];
    }

    const int lq  = tid & 15;        // l = lq and lq+16 within phase
    const int og  = tid >> 4;        // 0..17
    const int oc0 = og * 8;

    ull bp[4];
#pragma unroll
    for (int p = 0; p < 4; p++) bp[p] = pack2(b1[oc0 + 2*p], b1[oc0 + 2*p + 1]);

#pragma unroll 1
    for (int phase = 0; phase < 8; phase++) {
        const size_t lp = l0 + phase * 32;
        __syncthreads();
        for (int i = tid; i < 48 * 32; i += 288) {
            const int ic = i >> 5, j = i & 31;
            const float v = x[((size_t)b * C + ic) * LL + lp + j];
            Xd[ic][j] = make_float2(v, v);
        }
        __syncthreads();

        ull acc[4][2];
#pragma unroll
        for (int p = 0; p < 4; p++) { acc[p][0] = bp[p]; acc[p][1] = bp[p]; }

#pragma unroll 6
        for (int ic = 0; ic < 48; ic++) {
            const ull xa = *(const ull*)&Xd[ic][lq];
            const ull xb = *(const ull*)&Xd[ic][lq + 16];
            const ull* wrow = (const ull*)&Wt[ic][oc0];
#pragma unroll
            for (int p = 0; p < 4; p++) {
                const ull wp = wrow[p];
                fma2(acc[p][0], wp, xa);
                fma2(acc[p][1], wp, xb);
            }
        }

#pragma unroll
        for (int p = 0; p < 4; p++) {
            const float2 u0 = unpack2(acc[p][0]);   // l=lq   : {ocA, ocB}
            const float2 u1 = unpack2(acc[p][1]);   // l=lq+16: {ocA, ocB}
            float* oa = &g_qkv[((size_t)b * C3 + oc0 + 2*p    ) * LL + lp + lq];
            float* ob = &g_qkv[((size_t)b * C3 + oc0 + 2*p + 1) * LL + lp + lq];
            oa[0] = u0.x; oa[16] = u1.x;
            ob[0] = u0.y; ob[16] = u1.y;
        }
    }
}

// ---------------------------------------------------------------------------
// K2: depthwise 3x3x3, 144 channels. One warp per (b,ch,h); inline shuffles
// (low-register R1 form) + launch_bounds(256,3) -> 24 warps/SM, no spills.
// ---------------------------------------------------------------------------
__global__ __launch_bounds__(256, 3) void k2_dw(const float* __restrict__ wdw,
                                                const float* __restrict__ bdw) {
    const int gw   = blockIdx.x * 8 + (threadIdx.x >> 5);
    const int lane = threadIdx.x & 31;
    const int h  = gw % HD;
    const int t  = gw / HD;
    const int ch = t % C3;
    const int b  = t / C3;

    const float* base  = g_qkv + ((size_t)b * C3 + ch) * LL;
    float*       obase = g_dw  + ((size_t)b * C3 + ch) * LL;

    float w[27];
#pragma unroll
    for (int i = 0; i < 27; i++) w[i] = wdw[ch * 27 + i];
    const float bias = bdw[ch];

    float2 r[3][3];

    auto loadrow = [&](int d, int hh) -> float2 {
        const int hr = h + hh - 1;
        if (d < 0 || d >= DD || hr < 0 || hr >= HD) return make_float2(0.f, 0.f);
        return ((const float2*)(base + (size_t)d * HW + hr * WD))[lane];
    };

#pragma unroll
    for (int hh = 0; hh < 3; hh++) {
        r[0][hh] = make_float2(0.f, 0.f);
        r[1][hh] = loadrow(0, hh);
        r[2][hh] = loadrow(1, hh);
    }

    for (int d = 0; d < DD; d++) {
        float2 o = make_float2(bias, bias);
#pragma unroll
        for (int dd = 0; dd < 3; dd++) {
#pragma unroll
            for (int hh = 0; hh < 3; hh++) {
                const float2 rv = r[dd][hh];
                float xm = __shfl_up_sync(0xffffffffu, rv.y, 1);
                if (lane == 0) xm = 0.f;
                float xp = __shfl_down_sync(0xffffffffu, rv.x, 1);
                if (lane == 31) xp = 0.f;
                const int tb = (dd * 3 + hh) * 3;
                const float w0 = w[tb], w1 = w[tb + 1], w2 = w[tb + 2];
                o.x += w0 * xm   + w1 * rv.x + w2 * rv.y;
                o.y += w0 * rv.x + w1 * rv.y + w2 * xp;
            }
        }
        ((float2*)(obase + (size_t)d * HW + h * WD))[lane] = o;
#pragma unroll
        for (int hh = 0; hh < 3; hh++) {
            r[0][hh] = r[1][hh];
            r[1][hh] = r[2][hh];
            r[2][hh] = loadrow(d + 2, hh);
        }
    }
}

// ---------------------------------------------------------------------------
// K3: attn += q.k^T over l (R5 measured-best form, untouched)
// ---------------------------------------------------------------------------
__global__ __launch_bounds__(256) void k3_attn() {
    const int chunk = blockIdx.x;
    const int bh = blockIdx.y;
    const int b = bh / HEADS, hd = bh % HEADS;

    const float* qb = g_dw + ((size_t)b * C3 + hd * CPH) * LL + (size_t)chunk * 2048;
    const float* kb = qb + (size_t)C * LL;

    float acc[64];
#pragma unroll
    for (int i = 0; i < 64; i++) acc[i] = 0.f;

    for (int it = 0; it < 8; it++) {
        const int l = it * 256 + threadIdx.x;
        float q[8], k[8];
#pragma unroll
        for (int i = 0; i < 8; i++) {
            q[i] = qb[(size_t)i * LL + l];
            k[i] = kb[(size_t)i * LL + l];
        }
#pragma unroll
        for (int i = 0; i < 8; i++)
#pragma unroll
            for (int j = 0; j < 8; j++)
                acc[i * 8 + j] += q[i] * k[j];
    }

    __shared__ float red[64];
    if (threadIdx.x < 64) red[threadIdx.x] = 0.f;
    __syncthreads();
    const int lane = threadIdx.x & 31;
#pragma unroll
    for (int v = 0; v < 64; v++) {
        float s = acc[v];
#pragma unroll
        for (int off = 16; off > 0; off >>= 1)
            s += __shfl_xor_sync(0xffffffffu, s, off);
        if (lane == 0) atomicAdd(&red[v], s);
    }
    __syncthreads();
    if (threadIdx.x < 64)
        atomicAdd(&g_attn[bh * 64 + threadIdx.x], red[threadIdx.x]);
}

// ---------------------------------------------------------------------------
// K4: softmax(scale*attn + mask), fold proj into per-batch 48x48 Weff
// ---------------------------------------------------------------------------
__global__ __launch_bounds__(256) void k4_soft(const float* __restrict__ mask,
                                               const float* __restrict__ wproj) {
    const int tid = threadIdx.x;
    __shared__ float A[BATCH * HEADS * CPH * CPH];
    const float scale = 0.40824829046386307f;  // 6^-0.5

    if (tid < BATCH * HEADS * CPH) {
        const int b = tid / (HEADS * CPH);
        const int r = tid % (HEADS * CPH);
        const int hd = r / CPH, c = r % CPH;
        float v[8];
        float mx = -1e30f;
#pragma unroll
        for (int j = 0; j < 8; j++) {
            v[j] = g_attn[((b * HEADS + hd) * CPH + c) * CPH + j] * scale
                 + mask[(b * CPH + c) * CPH + j];
            mx = fmaxf(mx, v[j]);
        }
        float s = 0.f;
#pragma unroll
        for (int j = 0; j < 8; j++) { v[j] = expf(v[j] - mx); s += v[j]; }
        const float inv = 1.f / s;
#pragma unroll
        for (int j = 0; j < 8; j++)
            A[((b * HEADS + hd) * CPH + c) * CPH + j] = v[j] * inv;
    }
    __syncthreads();

    for (int i = tid; i < BATCH * C * C; i += 256) {
        const int b = i / (C * C);
        const int r = i % (C * C);
        const int oc = r / C, c2 = r % C;
        const int hd = c2 / CPH, j = c2 % CPH;
        float s = 0.f;
#pragma unroll
        for (int ii = 0; ii < 8; ii++)
            s += wproj[oc * C + hd * CPH + ii]
               * A[((b * HEADS + hd) * CPH + ii) * CPH + j];
        g_weff[i] = s;
    }
}

// ---------------------------------------------------------------------------
// K5: out = Weff[b] * v_dw + b_proj.  192 threads; X pre-duplicated; FFMA2.
// 4 phases of 64 l; thread = 2 l x 8 oc.
// ---------------------------------------------------------------------------
__global__ __launch_bounds__(192) void k5_proj(const float* __restrict__ bproj,
                                               float* __restrict__ outp) {
    __shared__ float  Wt[48][48];    // [c2][oc]
    __shared__ float2 Xd[48][64];    // [c2][l] duplicated

    const int b  = blockIdx.y;
    const size_t l0 = (size_t)blockIdx.x * 256;
    const int tid = threadIdx.x;

    for (int i = tid; i < C * C; i += 192) {
        int oc = i / 48, c2 = i % 48;
        Wt[c2][oc] = g_weff[b * C * C + i];
    }

    const int lq  = tid & 31;   // l = lq and lq+32 within phase
    const int og  = tid >> 5;   // 0..5
    const int oc0 = og * 8;

    ull bp[4];
#pragma unroll
    for (int p = 0; p < 4; p++) bp[p] = pack2(bproj[oc0 + 2*p], bproj[oc0 + 2*p + 1]);

#pragma unroll 1
    for (int phase = 0; phase < 4; phase++) {
        const size_t lp = l0 + phase * 64;
        __syncthreads();
        for (int i = tid; i < 48 * 64; i += 192) {
            const int ic = i >> 6, j = i & 63;
            const float v = g_dw[((size_t)b * C3 + 2 * C + ic) * LL + lp + j];
            Xd[ic][j] = make_float2(v, v);
        }
        __syncthreads();

        ull acc[4][2];
#pragma unroll
        for (int p = 0; p < 4; p++) { acc[p][0] = bp[p]; acc[p][1] = bp[p]; }

#pragma unroll 6
        for (int c2 = 0; c2 < 48; c2++) {
            const ull xa = *(const ull*)&Xd[c2][lq];
            const ull xb = *(const ull*)&Xd[c2][lq + 32];
            const ull* wrow = (const ull*)&Wt[c2][oc0];
#pragma unroll
            for (int p = 0; p < 4; p++) {
                const ull wp = wrow[p];
                fma2(acc[p][0], wp, xa);
                fma2(acc[p][1], wp, xb);
            }
        }

#pragma unroll
        for (int p = 0; p < 4; p++) {
            const float2 u0 = unpack2(acc[p][0]);
            const float2 u1 = unpack2(acc[p][1]);
            float* oa = &outp[((size_t)b * C + oc0 + 2*p    ) * LL + lp + lq];
            float* ob = &outp[((size_t)b * C + oc0 + 2*p + 1) * LL + lp + lq];
            oa[0] = u0.x; oa[32] = u1.x;
            ob[0] = u0.y; ob[32] = u1.y;
        }
    }
}

// ---------------------------------------------------------------------------
extern "C" void kernel_launch(void* const* d_in, const int* in_sizes, int n_in,
                              void* d_out, int out_size) {
    const float* x      = (const float*)d_in[0];
    const float* mask   = (const float*)d_in[1];
    const float* w_qkv1 = (const float*)d_in[2];
    const float* b_qkv1 = (const float*)d_in[3];
    const float* w_dw   = (const float*)d_in[4];
    const float* b_dw   = (const float*)d_in[5];
    const float* w_proj = (const float*)d_in[6];
    const float* b_proj = (const float*)d_in[7];
    float* out = (float*)d_out;

    k0_zero<<<1, BATCH * HEADS * CPH * CPH>>>();
    k1_qkv<<<dim3(LL / 256, BATCH), 288>>>(x, w_qkv1, b_qkv1);
    k2_dw<<<(BATCH * C3 * HD) / 8, 256>>>(w_dw, b_dw);
    k3_attn<<<dim3(LL / 2048, BATCH * HEADS), 256>>>();
    k4_soft<<<1, 256>>>(mask, w_proj);
    k5_proj<<<dim3(LL / 256, BATCH), 192>>>(b_proj, out);
}

// round 7
// speedup vs baseline: 1.2502x; 1.2502x over previous
#include <cuda_runtime.h>

#define BATCH 2
#define C     48
#define C3    144
#define DD    32
#define HD    64
#define WD    64
#define LL    (DD*HD*WD)   /* 131072 */
#define HW    (HD*WD)      /* 4096 */
#define HEADS 6
#define CPH   8

// ---- scratch ----
__device__ float g_qkv[(size_t)BATCH * C3 * LL];
__device__ float g_dw [(size_t)BATCH * C3 * LL];
__device__ float g_attn[BATCH * HEADS * CPH * CPH];
__device__ float g_weff[BATCH * C * C];

// ---------------------------------------------------------------------------
__global__ void k0_zero() {
    g_attn[threadIdx.x] = 0.0f;
}

// ---------------------------------------------------------------------------
// K1: qkv = W1[144x48] * x[48xL] + b1  (R2/R5 measured-best form, unchanged)
// ---------------------------------------------------------------------------
__global__ __launch_bounds__(288) void k1_qkv(const float* __restrict__ x,
                                              const float* __restrict__ w1,
                                              const float* __restrict__ b1) {
    __shared__ float  Wt[48][144];   // [ic][oc]
    __shared__ float4 Xs[48][16];    // [ic][l/4]

    const int b  = blockIdx.y;
    const size_t l0 = (size_t)blockIdx.x * 256;
    const int tid = threadIdx.x;

    for (int i = tid; i < C3 * C; i += 288) {
        int oc = i / 48, ic = i % 48;
        Wt[ic][oc] = w1[i];
    }

    const int lq  = tid & 15;
    const int og  = tid >> 4;
    const int oc0 = og * 8;

#pragma unroll 1
    for (int phase = 0; phase < 4; phase++) {
        const size_t lp = l0 + phase * 64;
        __syncthreads();
        for (int i = tid; i < 48 * 16; i += 288) {
            int ic = i >> 4, j = i & 15;
            Xs[ic][j] = *(const float4*)(x + ((size_t)b * C + ic) * LL + lp + j * 4);
        }
        __syncthreads();

        float4 acc[8];
#pragma unroll
        for (int j = 0; j < 8; j++) acc[j] = make_float4(0.f, 0.f, 0.f, 0.f);

#pragma unroll 4
        for (int ic = 0; ic < 48; ic++) {
            const float4 xv = Xs[ic][lq];
            const float4 wa = *(const float4*)&Wt[ic][oc0];
            const float4 wb = *(const float4*)&Wt[ic][oc0 + 4];
            const float wr[8] = {wa.x, wa.y, wa.z, wa.w, wb.x, wb.y, wb.z, wb.w};
#pragma unroll
            for (int j = 0; j < 8; j++) {
                acc[j].x += wr[j] * xv.x;
                acc[j].y += wr[j] * xv.y;
                acc[j].z += wr[j] * xv.z;
                acc[j].w += wr[j] * xv.w;
            }
        }

#pragma unroll
        for (int j = 0; j < 8; j++) {
            const int oc = oc0 + j;
            const float bb = b1[oc];
            float4 v = acc[j];
            v.x += bb; v.y += bb; v.z += bb; v.w += bb;
            *(float4*)&g_qkv[((size_t)b * C3 + oc) * LL + lp + lq * 4] = v;
        }
    }
}

// ---------------------------------------------------------------------------
// K2: depthwise 3x3x3, 144 channels. One warp per (b,ch,h). All 8 warps in a
// block share one (b,ch) (HD=64 divisible by 8), so the 27 weights + bias live
// in smem (broadcast LDS). Window regs only -> launch_bounds(256,4):
// 32 resident warps/SM (2x R5) on a latency-bound kernel.
// ---------------------------------------------------------------------------
__global__ __launch_bounds__(256, 4) void k2_dw(const float* __restrict__ wdw,
                                                const float* __restrict__ bdw) {
    const int gw   = blockIdx.x * 8 + (threadIdx.x >> 5);
    const int lane = threadIdx.x & 31;
    const int h  = gw % HD;
    const int t  = gw / HD;              // constant within block
    const int ch = t % C3;
    const int b  = t / C3;

    __shared__ float ws[28];              // 27 taps + bias at [27]
    if (threadIdx.x < 27) ws[threadIdx.x] = wdw[ch * 27 + threadIdx.x];
    if (threadIdx.x == 27) ws[27] = bdw[ch];
    __syncthreads();

    const float* base  = g_qkv + ((size_t)b * C3 + ch) * LL;
    float*       obase = g_dw  + ((size_t)b * C3 + ch) * LL;

    float2 r[3][3];

    auto loadrow = [&](int d, int hh) -> float2 {
        const int hr = h + hh - 1;
        if (d < 0 || d >= DD || hr < 0 || hr >= HD) return make_float2(0.f, 0.f);
        return ((const float2*)(base + (size_t)d * HW + hr * WD))[lane];
    };

#pragma unroll
    for (int hh = 0; hh < 3; hh++) {
        r[0][hh] = make_float2(0.f, 0.f);
        r[1][hh] = loadrow(0, hh);
        r[2][hh] = loadrow(1, hh);
    }

    for (int d = 0; d < DD; d++) {
        const float bias = ws[27];
        float2 o = make_float2(bias, bias);
#pragma unroll
        for (int dd = 0; dd < 3; dd++) {
#pragma unroll
            for (int hh = 0; hh < 3; hh++) {
                const float2 rv = r[dd][hh];
                float xm = __shfl_up_sync(0xffffffffu, rv.y, 1);
                if (lane == 0) xm = 0.f;
                float xp = __shfl_down_sync(0xffffffffu, rv.x, 1);
                if (lane == 31) xp = 0.f;
                const int tb = (dd * 3 + hh) * 3;
                const float w0 = ws[tb], w1 = ws[tb + 1], w2 = ws[tb + 2];
                o.x += w0 * xm   + w1 * rv.x + w2 * rv.y;
                o.y += w0 * rv.x + w1 * rv.y + w2 * xp;
            }
        }
        ((float2*)(obase + (size_t)d * HW + h * WD))[lane] = o;
#pragma unroll
        for (int hh = 0; hh < 3; hh++) {
            r[0][hh] = r[1][hh];
            r[1][hh] = r[2][hh];
            r[2][hh] = loadrow(d + 2, hh);
        }
    }
}

// ---------------------------------------------------------------------------
// K3: attn += q.k^T over l (R5 measured-best form, untouched)
// ---------------------------------------------------------------------------
__global__ __launch_bounds__(256) void k3_attn() {
    const int chunk = blockIdx.x;
    const int bh = blockIdx.y;
    const int b = bh / HEADS, hd = bh % HEADS;

    const float* qb = g_dw + ((size_t)b * C3 + hd * CPH) * LL + (size_t)chunk * 2048;
    const float* kb = qb + (size_t)C * LL;

    float acc[64];
#pragma unroll
    for (int i = 0; i < 64; i++) acc[i] = 0.f;

    for (int it = 0; it < 8; it++) {
        const int l = it * 256 + threadIdx.x;
        float q[8], k[8];
#pragma unroll
        for (int i = 0; i < 8; i++) {
            q[i] = qb[(size_t)i * LL + l];
            k[i] = kb[(size_t)i * LL + l];
        }
#pragma unroll
        for (int i = 0; i < 8; i++)
#pragma unroll
            for (int j = 0; j < 8; j++)
                acc[i * 8 + j] += q[i] * k[j];
    }

    __shared__ float red[64];
    if (threadIdx.x < 64) red[threadIdx.x] = 0.f;
    __syncthreads();
    const int lane = threadIdx.x & 31;
#pragma unroll
    for (int v = 0; v < 64; v++) {
        float s = acc[v];
#pragma unroll
        for (int off = 16; off > 0; off >>= 1)
            s += __shfl_xor_sync(0xffffffffu, s, off);
        if (lane == 0) atomicAdd(&red[v], s);
    }
    __syncthreads();
    if (threadIdx.x < 64)
        atomicAdd(&g_attn[bh * 64 + threadIdx.x], red[threadIdx.x]);
}

// ---------------------------------------------------------------------------
// K4: softmax(scale*attn + mask), fold proj into per-batch 48x48 Weff
// ---------------------------------------------------------------------------
__global__ __launch_bounds__(256) void k4_soft(const float* __restrict__ mask,
                                               const float* __restrict__ wproj) {
    const int tid = threadIdx.x;
    __shared__ float A[BATCH * HEADS * CPH * CPH];
    const float scale = 0.40824829046386307f;  // 6^-0.5

    if (tid < BATCH * HEADS * CPH) {
        const int b = tid / (HEADS * CPH);
        const int r = tid % (HEADS * CPH);
        const int hd = r / CPH, c = r % CPH;
        float v[8];
        float mx = -1e30f;
#pragma unroll
        for (int j = 0; j < 8; j++) {
            v[j] = g_attn[((b * HEADS + hd) * CPH + c) * CPH + j] * scale
                 + mask[(b * CPH + c) * CPH + j];
            mx = fmaxf(mx, v[j]);
        }
        float s = 0.f;
#pragma unroll
        for (int j = 0; j < 8; j++) { v[j] = expf(v[j] - mx); s += v[j]; }
        const float inv = 1.f / s;
#pragma unroll
        for (int j = 0; j < 8; j++)
            A[((b * HEADS + hd) * CPH + c) * CPH + j] = v[j] * inv;
    }
    __syncthreads();

    for (int i = tid; i < BATCH * C * C; i += 256) {
        const int b = i / (C * C);
        const int r = i % (C * C);
        const int oc = r / C, c2 = r % C;
        const int hd = c2 / CPH, j = c2 % CPH;
        float s = 0.f;
#pragma unroll
        for (int ii = 0; ii < 8; ii++)
            s += wproj[oc * C + hd * CPH + ii]
               * A[((b * HEADS + hd) * CPH + ii) * CPH + j];
        g_weff[i] = s;
    }
}

// ---------------------------------------------------------------------------
// K5: out = Weff[b] * v_dw + b_proj  (R2/R5 measured-best form, unchanged)
// ---------------------------------------------------------------------------
__global__ __launch_bounds__(192) void k5_proj(const float* __restrict__ bproj,
                                               float* __restrict__ outp) {
    __shared__ float  Wt[48][48];
    __shared__ float4 Vs[48][32];

    const int b  = blockIdx.y;
    const size_t l0 = (size_t)blockIdx.x * 256;
    const int tid = threadIdx.x;

    for (int i = tid; i < C * C; i += 192) {
        int oc = i / 48, c2 = i % 48;
        Wt[c2][oc] = g_weff[b * C * C + i];
    }

    const int lq  = tid & 31;
    const int og  = tid >> 5;
    const int oc0 = og * 8;

#pragma unroll 1
    for (int phase = 0; phase < 2; phase++) {
        const size_t lp = l0 + phase * 128;
        __syncthreads();
        for (int i = tid; i < 48 * 32; i += 192) {
            int ic = i >> 5, j = i & 31;
            Vs[ic][j] = *(const float4*)(g_dw + ((size_t)b * C3 + 2 * C + ic) * LL + lp + j * 4);
        }
        __syncthreads();

        float4 acc[8];
#pragma unroll
        for (int j = 0; j < 8; j++) acc[j] = make_float4(0.f, 0.f, 0.f, 0.f);

#pragma unroll 4
        for (int c2 = 0; c2 < 48; c2++) {
            const float4 xv = Vs[c2][lq];
            const float4 wa = *(const float4*)&Wt[c2][oc0];
            const float4 wb = *(const float4*)&Wt[c2][oc0 + 4];
            const float wr[8] = {wa.x, wa.y, wa.z, wa.w, wb.x, wb.y, wb.z, wb.w};
#pragma unroll
            for (int j = 0; j < 8; j++) {
                acc[j].x += wr[j] * xv.x;
                acc[j].y += wr[j] * xv.y;
                acc[j].z += wr[j] * xv.z;
                acc[j].w += wr[j] * xv.w;
            }
        }

#pragma unroll
        for (int j = 0; j < 8; j++) {
            const int oc = oc0 + j;
            const float bb = bproj[oc];
            float4 v = acc[j];
            v.x += bb; v.y += bb; v.z += bb; v.w += bb;
            *(float4*)&outp[((size_t)b * C + oc) * LL + lp + lq * 4] = v;
        }
    }
}

// ---------------------------------------------------------------------------
extern "C" void kernel_launch(void* const* d_in, const int* in_sizes, int n_in,
                              void* d_out, int out_size) {
    const float* x      = (const float*)d_in[0];
    const float* mask   = (const float*)d_in[1];
    const float* w_qkv1 = (const float*)d_in[2];
    const float* b_qkv1 = (const float*)d_in[3];
    const float* w_dw   = (const float*)d_in[4];
    const float* b_dw   = (const float*)d_in[5];
    const float* w_proj = (const float*)d_in[6];
    const float* b_proj = (const float*)d_in[7];
    float* out = (float*)d_out;

    k0_zero<<<1, BATCH * HEADS * CPH * CPH>>>();
    k1_qkv<<<dim3(LL / 256, BATCH), 288>>>(x, w_qkv1, b_qkv1);
    k2_dw<<<(BATCH * C3 * HD) / 8, 256>>>(w_dw, b_dw);
    k3_attn<<<dim3(LL / 2048, BATCH * HEADS), 256>>>();
    k4_soft<<<1, 256>>>(mask, w_proj);
    k5_proj<<<dim3(LL / 256, BATCH), 192>>>(b_proj, out);
}

// round 9
// speedup vs baseline: 1.3959x; 1.1165x over previous
#include <cuda_runtime.h>

#define BATCH 2
#define C     48
#define C3    144
#define DD    32
#define HD    64
#define WD    64
#define LL    (DD*HD*WD)   /* 131072 */
#define HW    (HD*WD)      /* 4096 */
#define HEADS 6
#define CPH   8

// ---- scratch ----
__device__ float g_qkv[(size_t)BATCH * C3 * LL];
__device__ float g_dw [(size_t)BATCH * C3 * LL];
__device__ float g_attn[BATCH * HEADS * CPH * CPH];
__device__ float g_weff[BATCH * C * C];

// ---------------------------------------------------------------------------
__global__ void k0_zero() {
    g_attn[threadIdx.x] = 0.0f;
}

// ---------------------------------------------------------------------------
// K1: qkv = W1[144x48] * x[48xL] + b1  (R2/R7 measured-best form, unchanged)
// ---------------------------------------------------------------------------
__global__ __launch_bounds__(288) void k1_qkv(const float* __restrict__ x,
                                              const float* __restrict__ w1,
                                              const float* __restrict__ b1) {
    __shared__ float  Wt[48][144];   // [ic][oc]
    __shared__ float4 Xs[48][16];    // [ic][l/4]

    const int b  = blockIdx.y;
    const size_t l0 = (size_t)blockIdx.x * 256;
    const int tid = threadIdx.x;

    for (int i = tid; i < C3 * C; i += 288) {
        int oc = i / 48, ic = i % 48;
        Wt[ic][oc] = w1[i];
    }

    const int lq  = tid & 15;
    const int og  = tid >> 4;
    const int oc0 = og * 8;

#pragma unroll 1
    for (int phase = 0; phase < 4; phase++) {
        const size_t lp = l0 + phase * 64;
        __syncthreads();
        for (int i = tid; i < 48 * 16; i += 288) {
            int ic = i >> 4, j = i & 15;
            Xs[ic][j] = *(const float4*)(x + ((size_t)b * C + ic) * LL + lp + j * 4);
        }
        __syncthreads();

        float4 acc[8];
#pragma unroll
        for (int j = 0; j < 8; j++) acc[j] = make_float4(0.f, 0.f, 0.f, 0.f);

#pragma unroll 4
        for (int ic = 0; ic < 48; ic++) {
            const float4 xv = Xs[ic][lq];
            const float4 wa = *(const float4*)&Wt[ic][oc0];
            const float4 wb = *(const float4*)&Wt[ic][oc0 + 4];
            const float wr[8] = {wa.x, wa.y, wa.z, wa.w, wb.x, wb.y, wb.z, wb.w};
#pragma unroll
            for (int j = 0; j < 8; j++) {
                acc[j].x += wr[j] * xv.x;
                acc[j].y += wr[j] * xv.y;
                acc[j].z += wr[j] * xv.z;
                acc[j].w += wr[j] * xv.w;
            }
        }

#pragma unroll
        for (int j = 0; j < 8; j++) {
            const int oc = oc0 + j;
            const float bb = b1[oc];
            float4 v = acc[j];
            v.x += bb; v.y += bb; v.z += bb; v.w += bb;
            *(float4*)&g_qkv[((size_t)b * C3 + oc) * LL + lp + lq * 4] = v;
        }
    }
}

// ---------------------------------------------------------------------------
// K2: depthwise 3x3x3, 144 channels. One warp per (b, ch, h-PAIR): computes
// output rows h0 and h0+1 per d, sharing the 4-row window (was 2x3 rows for
// two warps). Shifted edge values cached once at row-load time (4 shuffles/d
// instead of 36 for two rows). Weights+bias in smem. launch_bounds(256,3).
// ---------------------------------------------------------------------------
__global__ __launch_bounds__(256, 3) void k2_dw(const float* __restrict__ wdw,
                                                const float* __restrict__ bdw) {
    const int gw   = blockIdx.x * 8 + (threadIdx.x >> 5);
    const int lane = threadIdx.x & 31;
    const int hp = gw & 31;            // h-pair index 0..31
    const int t  = gw >> 5;            // (b*C3 + ch), constant per block
    const int ch = t % C3;
    const int b  = t / C3;
    const int h0 = hp * 2;

    __shared__ float ws[28];
    if (threadIdx.x < 27) ws[threadIdx.x] = wdw[ch * 27 + threadIdx.x];
    if (threadIdx.x == 27) ws[27] = bdw[ch];
    __syncthreads();

    const float* base  = g_qkv + ((size_t)b * C3 + ch) * LL;
    float*       obase = g_dw  + ((size_t)b * C3 + ch) * LL;

    float2 rv[3][4];   // [d-slot][row h0-1 .. h0+2]
    float  rl[3][4];   // value at w-1 (cached shuffle)
    float  rr[3][4];   // value at w+2 (cached shuffle)

    auto loadrow = [&](int d, int hh, int s) {
        const int hr = h0 + hh - 1;
        float2 v2;
        if (d < 0 || d >= DD || hr < 0 || hr >= HD) v2 = make_float2(0.f, 0.f);
        else v2 = ((const float2*)(base + (size_t)d * HW + hr * WD))[lane];
        float a = __shfl_up_sync(0xffffffffu, v2.y, 1);
        if (lane == 0) a = 0.f;
        float p = __shfl_down_sync(0xffffffffu, v2.x, 1);
        if (lane == 31) p = 0.f;
        rv[s][hh] = v2; rl[s][hh] = a; rr[s][hh] = p;
    };

#pragma unroll
    for (int hh = 0; hh < 4; hh++) {
        rv[0][hh] = make_float2(0.f, 0.f); rl[0][hh] = 0.f; rr[0][hh] = 0.f;
        loadrow(0, hh, 1);
        loadrow(1, hh, 2);
    }

    for (int d = 0; d < DD; d++) {
        const float bias = ws[27];
        float2 o0 = make_float2(bias, bias);   // output row h0
        float2 o1 = make_float2(bias, bias);   // output row h0+1
#pragma unroll
        for (int dd = 0; dd < 3; dd++) {
#pragma unroll
            for (int hh = 0; hh < 3; hh++) {
                const int tb = (dd * 3 + hh) * 3;
                const float w0 = ws[tb], w1 = ws[tb + 1], w2 = ws[tb + 2];
                {   // row hh contributes to output h0
                    const float2 v = rv[dd][hh];
                    o0.x += w0 * rl[dd][hh] + w1 * v.x + w2 * v.y;
                    o0.y += w0 * v.x        + w1 * v.y + w2 * rr[dd][hh];
                }
                {   // row hh+1 contributes to output h0+1
                    const float2 v = rv[dd][hh + 1];
                    o1.x += w0 * rl[dd][hh + 1] + w1 * v.x + w2 * v.y;
                    o1.y += w0 * v.x            + w1 * v.y + w2 * rr[dd][hh + 1];
                }
            }
        }
        ((float2*)(obase + (size_t)d * HW + h0 * WD))[lane]       = o0;
        ((float2*)(obase + (size_t)d * HW + (h0 + 1) * WD))[lane] = o1;
#pragma unroll
        for (int hh = 0; hh < 4; hh++) {
            rv[0][hh] = rv[1][hh]; rl[0][hh] = rl[1][hh]; rr[0][hh] = rr[1][hh];
            rv[1][hh] = rv[2][hh]; rl[1][hh] = rl[2][hh]; rr[1][hh] = rr[2][hh];
            loadrow(d + 2, hh, 2);
        }
    }
}

// ---------------------------------------------------------------------------
// K3: attn[b,h,c,d] += sum_l q[b,h,c,l] * k[b,h,d,l]
// q-channels split across blockIdx.z (4 each): 32 acc regs -> ~60 regs ->
// 4 CTAs/SM (was 2) on a latency-bound kernel.
// ---------------------------------------------------------------------------
__global__ __launch_bounds__(256) void k3_attn() {
    const int chunk = blockIdx.x;
    const int bh = blockIdx.y;
    const int z  = blockIdx.z;           // 0/1 -> q rows 0-3 / 4-7
    const int b = bh / HEADS, hd = bh % HEADS;

    const float* qb = g_dw + ((size_t)b * C3 + hd * CPH + 4 * z) * LL + (size_t)chunk * 2048;
    const float* kb = g_dw + ((size_t)b * C3 + C + hd * CPH) * LL + (size_t)chunk * 2048;

    float acc[32];
#pragma unroll
    for (int i = 0; i < 32; i++) acc[i] = 0.f;

    for (int it = 0; it < 8; it++) {
        const int l = it * 256 + threadIdx.x;
        float q[4], k[8];
#pragma unroll
        for (int i = 0; i < 4; i++) q[i] = qb[(size_t)i * LL + l];
#pragma unroll
        for (int i = 0; i < 8; i++) k[i] = kb[(size_t)i * LL + l];
#pragma unroll
        for (int i = 0; i < 4; i++)
#pragma unroll
            for (int j = 0; j < 8; j++)
                acc[i * 8 + j] += q[i] * k[j];
    }

    __shared__ float red[32];
    if (threadIdx.x < 32) red[threadIdx.x] = 0.f;
    __syncthreads();
    const int lane = threadIdx.x & 31;
#pragma unroll
    for (int v = 0; v < 32; v++) {
        float s = acc[v];
#pragma unroll
        for (int off = 16; off > 0; off >>= 1)
            s += __shfl_xor_sync(0xffffffffu, s, off);
        if (lane == 0) atomicAdd(&red[v], s);
    }
    __syncthreads();
    if (threadIdx.x < 32)
        atomicAdd(&g_attn[bh * 64 + 32 * z + threadIdx.x], red[threadIdx.x]);
}

// ---------------------------------------------------------------------------
// K4: softmax(scale*attn + mask), fold proj into per-batch 48x48 Weff
// ---------------------------------------------------------------------------
__global__ __launch_bounds__(256) void k4_soft(const float* __restrict__ mask,
                                               const float* __restrict__ wproj) {
    const int tid = threadIdx.x;
    __shared__ float A[BATCH * HEADS * CPH * CPH];
    const float scale = 0.40824829046386307f;  // 6^-0.5

    if (tid < BATCH * HEADS * CPH) {
        const int b = tid / (HEADS * CPH);
        const int r = tid % (HEADS * CPH);
        const int hd = r / CPH, c = r % CPH;
        float v[8];
        float mx = -1e30f;
#pragma unroll
        for (int j = 0; j < 8; j++) {
            v[j] = g_attn[((b * HEADS + hd) * CPH + c) * CPH + j] * scale
                 + mask[(b * CPH + c) * CPH + j];
            mx = fmaxf(mx, v[j]);
        }
        float s = 0.f;
#pragma unroll
        for (int j = 0; j < 8; j++) { v[j] = expf(v[j] - mx); s += v[j]; }
        const float inv = 1.f / s;
#pragma unroll
        for (int j = 0; j < 8; j++)
            A[((b * HEADS + hd) * CPH + c) * CPH + j] = v[j] * inv;
    }
    __syncthreads();

    for (int i = tid; i < BATCH * C * C; i += 256) {
        const int b = i / (C * C);
        const int r = i % (C * C);
        const int oc = r / C, c2 = r % C;
        const int hd = c2 / CPH, j = c2 % CPH;
        float s = 0.f;
#pragma unroll
        for (int ii = 0; ii < 8; ii++)
            s += wproj[oc * C + hd * CPH + ii]
               * A[((b * HEADS + hd) * CPH + ii) * CPH + j];
        g_weff[i] = s;
    }
}

// ---------------------------------------------------------------------------
// K5: out = Weff[b] * v_dw + b_proj  (R2/R7 measured-best, unchanged)
// ---------------------------------------------------------------------------
__global__ __launch_bounds__(192) void k5_proj(const float* __restrict__ bproj,
                                               float* __restrict__ outp) {
    __shared__ float  Wt[48][48];
    __shared__ float4 Vs[48][32];

    const int b  = blockIdx.y;
    const size_t l0 = (size_t)blockIdx.x * 256;
    const int tid = threadIdx.x;

    for (int i = tid; i < C * C; i += 192) {
        int oc = i / 48, c2 = i % 48;
        Wt[c2][oc] = g_weff[b * C * C + i];
    }

    const int lq  = tid & 31;
    const int og  = tid >> 5;
    const int oc0 = og * 8;

#pragma unroll 1
    for (int phase = 0; phase < 2; phase++) {
        const size_t lp = l0 + phase * 128;
        __syncthreads();
        for (int i = tid; i < 48 * 32; i += 192) {
            int ic = i >> 5, j = i & 31;
            Vs[ic][j] = *(const float4*)(g_dw + ((size_t)b * C3 + 2 * C + ic) * LL + lp + j * 4);
        }
        __syncthreads();

        float4 acc[8];
#pragma unroll
        for (int j = 0; j < 8; j++) acc[j] = make_float4(0.f, 0.f, 0.f, 0.f);

#pragma unroll 4
        for (int c2 = 0; c2 < 48; c2++) {
            const float4 xv = Vs[c2][lq];
            const float4 wa = *(const float4*)&Wt[c2][oc0];
            const float4 wb = *(const float4*)&Wt[c2][oc0 + 4];
            const float wr[8] = {wa.x, wa.y, wa.z, wa.w, wb.x, wb.y, wb.z, wb.w};
#pragma unroll
            for (int j = 0; j < 8; j++) {
                acc[j].x += wr[j] * xv.x;
                acc[j].y += wr[j] * xv.y;
                acc[j].z += wr[j] * xv.z;
                acc[j].w += wr[j] * xv.w;
            }
        }

#pragma unroll
        for (int j = 0; j < 8; j++) {
            const int oc = oc0 + j;
            const float bb = bproj[oc];
            float4 v = acc[j];
            v.x += bb; v.y += bb; v.z += bb; v.w += bb;
            *(float4*)&outp[((size_t)b * C + oc) * LL + lp + lq * 4] = v;
        }
    }
}

// ---------------------------------------------------------------------------
extern "C" void kernel_launch(void* const* d_in, const int* in_sizes, int n_in,
                              void* d_out, int out_size) {
    const float* x      = (const float*)d_in[0];
    const float* mask   = (const float*)d_in[1];
    const float* w_qkv1 = (const float*)d_in[2];
    const float* b_qkv1 = (const float*)d_in[3];
    const float* w_dw   = (const float*)d_in[4];
    const float* b_dw   = (const float*)d_in[5];
    const float* w_proj = (const float*)d_in[6];
    const float* b_proj = (const float*)d_in[7];
    float* out = (float*)d_out;

    k0_zero<<<1, BATCH * HEADS * CPH * CPH>>>();
    k1_qkv<<<dim3(LL / 256, BATCH), 288>>>(x, w_qkv1, b_qkv1);
    k2_dw<<<(BATCH * C3 * (HD / 2)) / 8, 256>>>(w_dw, b_dw);
    k3_attn<<<dim3(LL / 2048, BATCH * HEADS, 2), 256>>>();
    k4_soft<<<1, 256>>>(mask, w_proj);
    k5_proj<<<dim3(LL / 256, BATCH), 192>>>(b_proj, out);
}

// round 10
// speedup vs baseline: 1.4460x; 1.0359x over previous
#include <cuda_runtime.h>

#define BATCH 2
#define C     48
#define C3    144
#define DD    32
#define HD    64
#define WD    64
#define LL    (DD*HD*WD)   /* 131072 */
#define HW    (HD*WD)      /* 4096 */
#define HEADS 6
#define CPH   8

// ---- scratch ----
__device__ float g_qkv[(size_t)BATCH * C3 * LL];
__device__ float g_dw [(size_t)BATCH * C3 * LL];
__device__ float g_attn[BATCH * HEADS * CPH * CPH];
__device__ float g_weff[BATCH * C * C];

// ---------------------------------------------------------------------------
__global__ void k0_zero() {
    g_attn[threadIdx.x] = 0.0f;
}

// ---------------------------------------------------------------------------
// K1: qkv = W1[144x48] * x[48xL] + b1  (R2/R7 measured-best form, unchanged)
// ---------------------------------------------------------------------------
__global__ __launch_bounds__(288) void k1_qkv(const float* __restrict__ x,
                                              const float* __restrict__ w1,
                                              const float* __restrict__ b1) {
    __shared__ float  Wt[48][144];   // [ic][oc]
    __shared__ float4 Xs[48][16];    // [ic][l/4]

    const int b  = blockIdx.y;
    const size_t l0 = (size_t)blockIdx.x * 256;
    const int tid = threadIdx.x;

    for (int i = tid; i < C3 * C; i += 288) {
        int oc = i / 48, ic = i % 48;
        Wt[ic][oc] = w1[i];
    }

    const int lq  = tid & 15;
    const int og  = tid >> 4;
    const int oc0 = og * 8;

#pragma unroll 1
    for (int phase = 0; phase < 4; phase++) {
        const size_t lp = l0 + phase * 64;
        __syncthreads();
        for (int i = tid; i < 48 * 16; i += 288) {
            int ic = i >> 4, j = i & 15;
            Xs[ic][j] = *(const float4*)(x + ((size_t)b * C + ic) * LL + lp + j * 4);
        }
        __syncthreads();

        float4 acc[8];
#pragma unroll
        for (int j = 0; j < 8; j++) acc[j] = make_float4(0.f, 0.f, 0.f, 0.f);

#pragma unroll 4
        for (int ic = 0; ic < 48; ic++) {
            const float4 xv = Xs[ic][lq];
            const float4 wa = *(const float4*)&Wt[ic][oc0];
            const float4 wb = *(const float4*)&Wt[ic][oc0 + 4];
            const float wr[8] = {wa.x, wa.y, wa.z, wa.w, wb.x, wb.y, wb.z, wb.w};
#pragma unroll
            for (int j = 0; j < 8; j++) {
                acc[j].x += wr[j] * xv.x;
                acc[j].y += wr[j] * xv.y;
                acc[j].z += wr[j] * xv.z;
                acc[j].w += wr[j] * xv.w;
            }
        }

#pragma unroll
        for (int j = 0; j < 8; j++) {
            const int oc = oc0 + j;
            const float bb = b1[oc];
            float4 v = acc[j];
            v.x += bb; v.y += bb; v.z += bb; v.w += bb;
            *(float4*)&g_qkv[((size_t)b * C3 + oc) * LL + lp + lq * 4] = v;
        }
    }
}

// ---------------------------------------------------------------------------
// K2: depthwise 3x3x3, 144 channels. One warp per (b, ch, h-pair) as in R9,
// but the d-loop uses STATIC SLOT ROTATION (unroll-by-3 with compile-time
// rotated slot indices) so the rolling window needs zero register-shift MOVs.
// ---------------------------------------------------------------------------
__global__ __launch_bounds__(256, 3) void k2_dw(const float* __restrict__ wdw,
                                                const float* __restrict__ bdw) {
    const int gw   = blockIdx.x * 8 + (threadIdx.x >> 5);
    const int lane = threadIdx.x & 31;
    const int hp = gw & 31;            // h-pair index 0..31
    const int t  = gw >> 5;            // (b*C3 + ch), constant per block
    const int ch = t % C3;
    const int b  = t / C3;
    const int h0 = hp * 2;

    __shared__ float ws[28];
    if (threadIdx.x < 27) ws[threadIdx.x] = wdw[ch * 27 + threadIdx.x];
    if (threadIdx.x == 27) ws[27] = bdw[ch];
    __syncthreads();

    const float* base  = g_qkv + ((size_t)b * C3 + ch) * LL;
    float*       obase = g_dw  + ((size_t)b * C3 + ch) * LL;

    float2 rv[3][4];   // [slot][row h0-1 .. h0+2]
    float  rl[3][4];   // value at w-1 (cached shuffle)
    float  rr[3][4];   // value at w+2 (cached shuffle)

    auto loadrow = [&](int d, int hh, int s) {
        const int hr = h0 + hh - 1;
        float2 v2;
        if (d < 0 || d >= DD || hr < 0 || hr >= HD) v2 = make_float2(0.f, 0.f);
        else v2 = ((const float2*)(base + (size_t)d * HW + hr * WD))[lane];
        float a = __shfl_up_sync(0xffffffffu, v2.y, 1);
        if (lane == 0) a = 0.f;
        float p = __shfl_down_sync(0xffffffffu, v2.x, 1);
        if (lane == 31) p = 0.f;
        rv[s][hh] = v2; rl[s][hh] = a; rr[s][hh] = p;
    };

#pragma unroll
    for (int hh = 0; hh < 4; hh++) {
        rv[0][hh] = make_float2(0.f, 0.f); rl[0][hh] = 0.f; rr[0][hh] = 0.f;
        loadrow(0, hh, 1);
        loadrow(1, hh, 2);
    }

    // one dd-plane of taps from slot SL (compile-time), weight base dd
#define K2_DD(SL, dd)                                                        \
    {                                                                        \
        _Pragma("unroll")                                                    \
        for (int hh = 0; hh < 3; hh++) {                                     \
            const int tb = ((dd) * 3 + hh) * 3;                              \
            const float w0 = ws[tb], w1 = ws[tb + 1], w2 = ws[tb + 2];       \
            {                                                                \
                const float2 v = rv[SL][hh];                                 \
                o0.x += w0 * rl[SL][hh] + w1 * v.x + w2 * v.y;               \
                o0.y += w0 * v.x        + w1 * v.y + w2 * rr[SL][hh];        \
            }                                                                \
            {                                                                \
                const float2 v = rv[SL][hh + 1];                             \
                o1.x += w0 * rl[SL][hh + 1] + w1 * v.x + w2 * v.y;           \
                o1.y += w0 * v.x            + w1 * v.y + w2 * rr[SL][hh + 1];\
            }                                                                \
        }                                                                    \
    }

    // full d-step: compute from slots (S0=d-1, S1=d, S2=d+1), store, then
    // load d+2 into S0 (overwriting d-1) -- static rotation, no MOVs.
#define K2_BODY(dcur, S0, S1, S2)                                            \
    {                                                                        \
        const float bias = ws[27];                                           \
        float2 o0 = make_float2(bias, bias);                                 \
        float2 o1 = make_float2(bias, bias);                                 \
        K2_DD(S0, 0)                                                         \
        K2_DD(S1, 1)                                                         \
        K2_DD(S2, 2)                                                         \
        ((float2*)(obase + (size_t)(dcur) * HW + h0 * WD))[lane]       = o0; \
        ((float2*)(obase + (size_t)(dcur) * HW + (h0 + 1) * WD))[lane] = o1; \
        _Pragma("unroll")                                                    \
        for (int hh = 0; hh < 4; hh++) loadrow((dcur) + 2, hh, S0);          \
    }

#pragma unroll 1
    for (int d = 0; d < 30; d += 3) {
        K2_BODY(d,     0, 1, 2)
        K2_BODY(d + 1, 1, 2, 0)
        K2_BODY(d + 2, 2, 0, 1)
    }
    K2_BODY(30, 0, 1, 2)
    K2_BODY(31, 1, 2, 0)
#undef K2_BODY
#undef K2_DD
}

// ---------------------------------------------------------------------------
// K3: attn[b,h,c,d] += sum_l q[b,h,c,l] * k[b,h,d,l]  (R9 measured-best)
// ---------------------------------------------------------------------------
__global__ __launch_bounds__(256) void k3_attn() {
    const int chunk = blockIdx.x;
    const int bh = blockIdx.y;
    const int z  = blockIdx.z;           // 0/1 -> q rows 0-3 / 4-7
    const int b = bh / HEADS, hd = bh % HEADS;

    const float* qb = g_dw + ((size_t)b * C3 + hd * CPH + 4 * z) * LL + (size_t)chunk * 2048;
    const float* kb = g_dw + ((size_t)b * C3 + C + hd * CPH) * LL + (size_t)chunk * 2048;

    float acc[32];
#pragma unroll
    for (int i = 0; i < 32; i++) acc[i] = 0.f;

    for (int it = 0; it < 8; it++) {
        const int l = it * 256 + threadIdx.x;
        float q[4], k[8];
#pragma unroll
        for (int i = 0; i < 4; i++) q[i] = qb[(size_t)i * LL + l];
#pragma unroll
        for (int i = 0; i < 8; i++) k[i] = kb[(size_t)i * LL + l];
#pragma unroll
        for (int i = 0; i < 4; i++)
#pragma unroll
            for (int j = 0; j < 8; j++)
                acc[i * 8 + j] += q[i] * k[j];
    }

    __shared__ float red[32];
    if (threadIdx.x < 32) red[threadIdx.x] = 0.f;
    __syncthreads();
    const int lane = threadIdx.x & 31;
#pragma unroll
    for (int v = 0; v < 32; v++) {
        float s = acc[v];
#pragma unroll
        for (int off = 16; off > 0; off >>= 1)
            s += __shfl_xor_sync(0xffffffffu, s, off);
        if (lane == 0) atomicAdd(&red[v], s);
    }
    __syncthreads();
    if (threadIdx.x < 32)
        atomicAdd(&g_attn[bh * 64 + 32 * z + threadIdx.x], red[threadIdx.x]);
}

// ---------------------------------------------------------------------------
// K4: softmax(scale*attn + mask), fold proj into per-batch 48x48 Weff
// ---------------------------------------------------------------------------
__global__ __launch_bounds__(256) void k4_soft(const float* __restrict__ mask,
                                               const float* __restrict__ wproj) {
    const int tid = threadIdx.x;
    __shared__ float A[BATCH * HEADS * CPH * CPH];
    const float scale = 0.40824829046386307f;  // 6^-0.5

    if (tid < BATCH * HEADS * CPH) {
        const int b = tid / (HEADS * CPH);
        const int r = tid % (HEADS * CPH);
        const int hd = r / CPH, c = r % CPH;
        float v[8];
        float mx = -1e30f;
#pragma unroll
        for (int j = 0; j < 8; j++) {
            v[j] = g_attn[((b * HEADS + hd) * CPH + c) * CPH + j] * scale
                 + mask[(b * CPH + c) * CPH + j];
            mx = fmaxf(mx, v[j]);
        }
        float s = 0.f;
#pragma unroll
        for (int j = 0; j < 8; j++) { v[j] = expf(v[j] - mx); s += v[j]; }
        const float inv = 1.f / s;
#pragma unroll
        for (int j = 0; j < 8; j++)
            A[((b * HEADS + hd) * CPH + c) * CPH + j] = v[j] * inv;
    }
    __syncthreads();

    for (int i = tid; i < BATCH * C * C; i += 256) {
        const int b = i / (C * C);
        const int r = i % (C * C);
        const int oc = r / C, c2 = r % C;
        const int hd = c2 / CPH, j = c2 % CPH;
        float s = 0.f;
#pragma unroll
        for (int ii = 0; ii < 8; ii++)
            s += wproj[oc * C + hd * CPH + ii]
               * A[((b * HEADS + hd) * CPH + ii) * CPH + j];
        g_weff[i] = s;
    }
}

// ---------------------------------------------------------------------------
// K5: out = Weff[b] * v_dw + b_proj  (R2/R7 measured-best, unchanged)
// ---------------------------------------------------------------------------
__global__ __launch_bounds__(192) void k5_proj(const float* __restrict__ bproj,
                                               float* __restrict__ outp) {
    __shared__ float  Wt[48][48];
    __shared__ float4 Vs[48][32];

    const int b  = blockIdx.y;
    const size_t l0 = (size_t)blockIdx.x * 256;
    const int tid = threadIdx.x;

    for (int i = tid; i < C * C; i += 192) {
        int oc = i / 48, c2 = i % 48;
        Wt[c2][oc] = g_weff[b * C * C + i];
    }

    const int lq  = tid & 31;
    const int og  = tid >> 5;
    const int oc0 = og * 8;

#pragma unroll 1
    for (int phase = 0; phase < 2; phase++) {
        const size_t lp = l0 + phase * 128;
        __syncthreads();
        for (int i = tid; i < 48 * 32; i += 192) {
            int ic = i >> 5, j = i & 31;
            Vs[ic][j] = *(const float4*)(g_dw + ((size_t)b * C3 + 2 * C + ic) * LL + lp + j * 4);
        }
        __syncthreads();

        float4 acc[8];
#pragma unroll
        for (int j = 0; j < 8; j++) acc[j] = make_float4(0.f, 0.f, 0.f, 0.f);

#pragma unroll 4
        for (int c2 = 0; c2 < 48; c2++) {
            const float4 xv = Vs[c2][lq];
            const float4 wa = *(const float4*)&Wt[c2][oc0];
            const float4 wb = *(const float4*)&Wt[c2][oc0 + 4];
            const float wr[8] = {wa.x, wa.y, wa.z, wa.w, wb.x, wb.y, wb.z, wb.w};
#pragma unroll
            for (int j = 0; j < 8; j++) {
                acc[j].x += wr[j] * xv.x;
                acc[j].y += wr[j] * xv.y;
                acc[j].z += wr[j] * xv.z;
                acc[j].w += wr[j] * xv.w;
            }
        }

#pragma unroll
        for (int j = 0; j < 8; j++) {
            const int oc = oc0 + j;
            const float bb = bproj[oc];
            float4 v = acc[j];
            v.x += bb; v.y += bb; v.z += bb; v.w += bb;
            *(float4*)&outp[((size_t)b * C + oc) * LL + lp + lq * 4] = v;
        }
    }
}

// ---------------------------------------------------------------------------
extern "C" void kernel_launch(void* const* d_in, const int* in_sizes, int n_in,
                              void* d_out, int out_size) {
    const float* x      = (const float*)d_in[0];
    const float* mask   = (const float*)d_in[1];
    const float* w_qkv1 = (const float*)d_in[2];
    const float* b_qkv1 = (const float*)d_in[3];
    const float* w_dw   = (const float*)d_in[4];
    const float* b_dw   = (const float*)d_in[5];
    const float* w_proj = (const float*)d_in[6];
    const float* b_proj = (const float*)d_in[7];
    float* out = (float*)d_out;

    k0_zero<<<1, BATCH * HEADS * CPH * CPH>>>();
    k1_qkv<<<dim3(LL / 256, BATCH), 288>>>(x, w_qkv1, b_qkv1);
    k2_dw<<<(BATCH * C3 * (HD / 2)) / 8, 256>>>(w_dw, b_dw);
    k3_attn<<<dim3(LL / 2048, BATCH * HEADS, 2), 256>>>();
    k4_soft<<<1, 256>>>(mask, w_proj);
    k5_proj<<<dim3(LL / 256, BATCH), 192>>>(b_proj, out);
}

// round 11
// speedup vs baseline: 1.4781x; 1.0222x over previous
#include <cuda_runtime.h>

#define BATCH 2
#define C     48
#define C3    144
#define DD    32
#define HD    64
#define WD    64
#define LL    (DD*HD*WD)   /* 131072 */
#define HW    (HD*WD)      /* 4096 */
#define HEADS 6
#define CPH   8

// ---- scratch ----
__device__ float g_qkv[(size_t)BATCH * C3 * LL];
__device__ float g_dw [(size_t)BATCH * C3 * LL];
__device__ float g_attn[BATCH * HEADS * CPH * CPH];
__device__ float g_weff[BATCH * C * C];

// ---------------------------------------------------------------------------
__global__ void k0_zero() {
    g_attn[threadIdx.x] = 0.0f;
}

// ---------------------------------------------------------------------------
// K1: qkv = W1[144x48] * x[48xL] + b1  (R2/R7 measured-best form, unchanged)
// ---------------------------------------------------------------------------
__global__ __launch_bounds__(288) void k1_qkv(const float* __restrict__ x,
                                              const float* __restrict__ w1,
                                              const float* __restrict__ b1) {
    __shared__ float  Wt[48][144];   // [ic][oc]
    __shared__ float4 Xs[48][16];    // [ic][l/4]

    const int b  = blockIdx.y;
    const size_t l0 = (size_t)blockIdx.x * 256;
    const int tid = threadIdx.x;

    for (int i = tid; i < C3 * C; i += 288) {
        int oc = i / 48, ic = i % 48;
        Wt[ic][oc] = w1[i];
    }

    const int lq  = tid & 15;
    const int og  = tid >> 4;
    const int oc0 = og * 8;

#pragma unroll 1
    for (int phase = 0; phase < 4; phase++) {
        const size_t lp = l0 + phase * 64;
        __syncthreads();
        for (int i = tid; i < 48 * 16; i += 288) {
            int ic = i >> 4, j = i & 15;
            Xs[ic][j] = *(const float4*)(x + ((size_t)b * C + ic) * LL + lp + j * 4);
        }
        __syncthreads();

        float4 acc[8];
#pragma unroll
        for (int j = 0; j < 8; j++) acc[j] = make_float4(0.f, 0.f, 0.f, 0.f);

#pragma unroll 4
        for (int ic = 0; ic < 48; ic++) {
            const float4 xv = Xs[ic][lq];
            const float4 wa = *(const float4*)&Wt[ic][oc0];
            const float4 wb = *(const float4*)&Wt[ic][oc0 + 4];
            const float wr[8] = {wa.x, wa.y, wa.z, wa.w, wb.x, wb.y, wb.z, wb.w};
#pragma unroll
            for (int j = 0; j < 8; j++) {
                acc[j].x += wr[j] * xv.x;
                acc[j].y += wr[j] * xv.y;
                acc[j].z += wr[j] * xv.z;
                acc[j].w += wr[j] * xv.w;
            }
        }

#pragma unroll
        for (int j = 0; j < 8; j++) {
            const int oc = oc0 + j;
            const float bb = b1[oc];
            float4 v = acc[j];
            v.x += bb; v.y += bb; v.z += bb; v.w += bb;
            *(float4*)&g_qkv[((size_t)b * C3 + oc) * LL + lp + lq * 4] = v;
        }
    }
}

// ---------------------------------------------------------------------------
// K2: depthwise 3x3x3 over a channel RANGE [ch_off, ch_off+CHCNT) per batch.
// R10 form (h-pair per warp, static slot rotation, smem weights); channel
// subsetting lets the v-part run on a side stream concurrent with qk+attn.
// ---------------------------------------------------------------------------
template <int CHCNT>
__global__ __launch_bounds__(256, 3) void k2_dw(const float* __restrict__ wdw,
                                                const float* __restrict__ bdw,
                                                int ch_off) {
    const int gw   = blockIdx.x * 8 + (threadIdx.x >> 5);
    const int lane = threadIdx.x & 31;
    const int hp = gw & 31;            // h-pair index 0..31
    const int t  = gw >> 5;            // constant per block
    const int ch = ch_off + t % CHCNT;
    const int b  = t / CHCNT;
    const int h0 = hp * 2;

    __shared__ float ws[28];
    if (threadIdx.x < 27) ws[threadIdx.x] = wdw[ch * 27 + threadIdx.x];
    if (threadIdx.x == 27) ws[27] = bdw[ch];
    __syncthreads();

    const float* base  = g_qkv + ((size_t)b * C3 + ch) * LL;
    float*       obase = g_dw  + ((size_t)b * C3 + ch) * LL;

    float2 rv[3][4];   // [slot][row h0-1 .. h0+2]
    float  rl[3][4];   // value at w-1 (cached shuffle)
    float  rr[3][4];   // value at w+2 (cached shuffle)

    auto loadrow = [&](int d, int hh, int s) {
        const int hr = h0 + hh - 1;
        float2 v2;
        if (d < 0 || d >= DD || hr < 0 || hr >= HD) v2 = make_float2(0.f, 0.f);
        else v2 = ((const float2*)(base + (size_t)d * HW + hr * WD))[lane];
        float a = __shfl_up_sync(0xffffffffu, v2.y, 1);
        if (lane == 0) a = 0.f;
        float p = __shfl_down_sync(0xffffffffu, v2.x, 1);
        if (lane == 31) p = 0.f;
        rv[s][hh] = v2; rl[s][hh] = a; rr[s][hh] = p;
    };

#pragma unroll
    for (int hh = 0; hh < 4; hh++) {
        rv[0][hh] = make_float2(0.f, 0.f); rl[0][hh] = 0.f; rr[0][hh] = 0.f;
        loadrow(0, hh, 1);
        loadrow(1, hh, 2);
    }

#define K2_DD(SL, dd)                                                        \
    {                                                                        \
        _Pragma("unroll")                                                    \
        for (int hh = 0; hh < 3; hh++) {                                     \
            const int tb = ((dd) * 3 + hh) * 3;                              \
            const float w0 = ws[tb], w1 = ws[tb + 1], w2 = ws[tb + 2];       \
            {                                                                \
                const float2 v = rv[SL][hh];                                 \
                o0.x += w0 * rl[SL][hh] + w1 * v.x + w2 * v.y;               \
                o0.y += w0 * v.x        + w1 * v.y + w2 * rr[SL][hh];        \
            }                                                                \
            {                                                                \
                const float2 v = rv[SL][hh + 1];                             \
                o1.x += w0 * rl[SL][hh + 1] + w1 * v.x + w2 * v.y;           \
                o1.y += w0 * v.x            + w1 * v.y + w2 * rr[SL][hh + 1];\
            }                                                                \
        }                                                                    \
    }

#define K2_BODY(dcur, S0, S1, S2)                                            \
    {                                                                        \
        const float bias = ws[27];                                           \
        float2 o0 = make_float2(bias, bias);                                 \
        float2 o1 = make_float2(bias, bias);                                 \
        K2_DD(S0, 0)                                                         \
        K2_DD(S1, 1)                                                         \
        K2_DD(S2, 2)                                                         \
        ((float2*)(obase + (size_t)(dcur) * HW + h0 * WD))[lane]       = o0; \
        ((float2*)(obase + (size_t)(dcur) * HW + (h0 + 1) * WD))[lane] = o1; \
        _Pragma("unroll")                                                    \
        for (int hh = 0; hh < 4; hh++) loadrow((dcur) + 2, hh, S0);          \
    }

#pragma unroll 1
    for (int d = 0; d < 30; d += 3) {
        K2_BODY(d,     0, 1, 2)
        K2_BODY(d + 1, 1, 2, 0)
        K2_BODY(d + 2, 2, 0, 1)
    }
    K2_BODY(30, 0, 1, 2)
    K2_BODY(31, 1, 2, 0)
#undef K2_BODY
#undef K2_DD
}

// ---------------------------------------------------------------------------
// K3: attn[b,h,c,d] += sum_l q[b,h,c,l] * k[b,h,d,l]  (R9 measured-best)
// ---------------------------------------------------------------------------
__global__ __launch_bounds__(256) void k3_attn() {
    const int chunk = blockIdx.x;
    const int bh = blockIdx.y;
    const int z  = blockIdx.z;           // 0/1 -> q rows 0-3 / 4-7
    const int b = bh / HEADS, hd = bh % HEADS;

    const float* qb = g_dw + ((size_t)b * C3 + hd * CPH + 4 * z) * LL + (size_t)chunk * 2048;
    const float* kb = g_dw + ((size_t)b * C3 + C + hd * CPH) * LL + (size_t)chunk * 2048;

    float acc[32];
#pragma unroll
    for (int i = 0; i < 32; i++) acc[i] = 0.f;

    for (int it = 0; it < 8; it++) {
        const int l = it * 256 + threadIdx.x;
        float q[4], k[8];
#pragma unroll
        for (int i = 0; i < 4; i++) q[i] = qb[(size_t)i * LL + l];
#pragma unroll
        for (int i = 0; i < 8; i++) k[i] = kb[(size_t)i * LL + l];
#pragma unroll
        for (int i = 0; i < 4; i++)
#pragma unroll
            for (int j = 0; j < 8; j++)
                acc[i * 8 + j] += q[i] * k[j];
    }

    __shared__ float red[32];
    if (threadIdx.x < 32) red[threadIdx.x] = 0.f;
    __syncthreads();
    const int lane = threadIdx.x & 31;
#pragma unroll
    for (int v = 0; v < 32; v++) {
        float s = acc[v];
#pragma unroll
        for (int off = 16; off > 0; off >>= 1)
            s += __shfl_xor_sync(0xffffffffu, s, off);
        if (lane == 0) atomicAdd(&red[v], s);
    }
    __syncthreads();
    if (threadIdx.x < 32)
        atomicAdd(&g_attn[bh * 64 + 32 * z + threadIdx.x], red[threadIdx.x]);
}

// ---------------------------------------------------------------------------
// K4: softmax(scale*attn + mask), fold proj into per-batch 48x48 Weff
// ---------------------------------------------------------------------------
__global__ __launch_bounds__(256) void k4_soft(const float* __restrict__ mask,
                                               const float* __restrict__ wproj) {
    const int tid = threadIdx.x;
    __shared__ float A[BATCH * HEADS * CPH * CPH];
    const float scale = 0.40824829046386307f;  // 6^-0.5

    if (tid < BATCH * HEADS * CPH) {
        const int b = tid / (HEADS * CPH);
        const int r = tid % (HEADS * CPH);
        const int hd = r / CPH, c = r % CPH;
        float v[8];
        float mx = -1e30f;
#pragma unroll
        for (int j = 0; j < 8; j++) {
            v[j] = g_attn[((b * HEADS + hd) * CPH + c) * CPH + j] * scale
                 + mask[(b * CPH + c) * CPH + j];
            mx = fmaxf(mx, v[j]);
        }
        float s = 0.f;
#pragma unroll
        for (int j = 0; j < 8; j++) { v[j] = expf(v[j] - mx); s += v[j]; }
        const float inv = 1.f / s;
#pragma unroll
        for (int j = 0; j < 8; j++)
            A[((b * HEADS + hd) * CPH + c) * CPH + j] = v[j] * inv;
    }
    __syncthreads();

    for (int i = tid; i < BATCH * C * C; i += 256) {
        const int b = i / (C * C);
        const int r = i % (C * C);
        const int oc = r / C, c2 = r % C;
        const int hd = c2 / CPH, j = c2 % CPH;
        float s = 0.f;
#pragma unroll
        for (int ii = 0; ii < 8; ii++)
            s += wproj[oc * C + hd * CPH + ii]
               * A[((b * HEADS + hd) * CPH + ii) * CPH + j];
        g_weff[i] = s;
    }
}

// ---------------------------------------------------------------------------
// K5: out = Weff[b] * v_dw + b_proj  (R2/R7 measured-best, unchanged)
// ---------------------------------------------------------------------------
__global__ __launch_bounds__(192) void k5_proj(const float* __restrict__ bproj,
                                               float* __restrict__ outp) {
    __shared__ float  Wt[48][48];
    __shared__ float4 Vs[48][32];

    const int b  = blockIdx.y;
    const size_t l0 = (size_t)blockIdx.x * 256;
    const int tid = threadIdx.x;

    for (int i = tid; i < C * C; i += 192) {
        int oc = i / 48, c2 = i % 48;
        Wt[c2][oc] = g_weff[b * C * C + i];
    }

    const int lq  = tid & 31;
    const int og  = tid >> 5;
    const int oc0 = og * 8;

#pragma unroll 1
    for (int phase = 0; phase < 2; phase++) {
        const size_t lp = l0 + phase * 128;
        __syncthreads();
        for (int i = tid; i < 48 * 32; i += 192) {
            int ic = i >> 5, j = i & 31;
            Vs[ic][j] = *(const float4*)(g_dw + ((size_t)b * C3 + 2 * C + ic) * LL + lp + j * 4);
        }
        __syncthreads();

        float4 acc[8];
#pragma unroll
        for (int j = 0; j < 8; j++) acc[j] = make_float4(0.f, 0.f, 0.f, 0.f);

#pragma unroll 4
        for (int c2 = 0; c2 < 48; c2++) {
            const float4 xv = Vs[c2][lq];
            const float4 wa = *(const float4*)&Wt[c2][oc0];
            const float4 wb = *(const float4*)&Wt[c2][oc0 + 4];
            const float wr[8] = {wa.x, wa.y, wa.z, wa.w, wb.x, wb.y, wb.z, wb.w};
#pragma unroll
            for (int j = 0; j < 8; j++) {
                acc[j].x += wr[j] * xv.x;
                acc[j].y += wr[j] * xv.y;
                acc[j].z += wr[j] * xv.z;
                acc[j].w += wr[j] * xv.w;
            }
        }

#pragma unroll
        for (int j = 0; j < 8; j++) {
            const int oc = oc0 + j;
            const float bb = bproj[oc];
            float4 v = acc[j];
            v.x += bb; v.y += bb; v.z += bb; v.w += bb;
            *(float4*)&outp[((size_t)b * C + oc) * LL + lp + lq * 4] = v;
        }
    }
}

// ---------------------------------------------------------------------------
// Launch: fork k2v onto a side stream (event fork-join, capture-legal).
//   stream0: k0, k1 --eA--> k2qk -> k3 -> k4 --(wait eB)--> k5
//   s1:            (wait eA) k2v --eB-->
// Streams/events created fresh per call and intentionally leaked (the
// harness calls kernel_launch only a couple of times; destroying objects
// mid-capture is illegal, and no device memory is allocated here).
// ---------------------------------------------------------------------------
extern "C" void kernel_launch(void* const* d_in, const int* in_sizes, int n_in,
                              void* d_out, int out_size) {
    const float* x      = (const float*)d_in[0];
    const float* mask   = (const float*)d_in[1];
    const float* w_qkv1 = (const float*)d_in[2];
    const float* b_qkv1 = (const float*)d_in[3];
    const float* w_dw   = (const float*)d_in[4];
    const float* b_dw   = (const float*)d_in[5];
    const float* w_proj = (const float*)d_in[6];
    const float* b_proj = (const float*)d_in[7];
    float* out = (float*)d_out;

    cudaStream_t s1;
    cudaEvent_t eA, eB;
    cudaStreamCreate(&s1);
    cudaEventCreateWithFlags(&eA, cudaEventDisableTiming);
    cudaEventCreateWithFlags(&eB, cudaEventDisableTiming);

    k0_zero<<<1, BATCH * HEADS * CPH * CPH>>>();
    k1_qkv<<<dim3(LL / 256, BATCH), 288>>>(x, w_qkv1, b_qkv1);

    cudaEventRecord(eA, 0);
    cudaStreamWaitEvent(s1, eA, 0);

    // side stream: v-channel depthwise (independent of attention path)
    k2_dw<C><<<(BATCH * C * (HD / 2)) / 8, 256, 0, s1>>>(w_dw, b_dw, 2 * C);
    cudaEventRecord(eB, s1);

    // main stream: qk depthwise -> attention -> softmax/proj-fold
    k2_dw<2 * C><<<(BATCH * 2 * C * (HD / 2)) / 8, 256>>>(w_dw, b_dw, 0);
    k3_attn<<<dim3(LL / 2048, BATCH * HEADS, 2), 256>>>();
    k4_soft<<<1, 256>>>(mask, w_proj);

    cudaStreamWaitEvent(0, eB, 0);
    k5_proj<<<dim3(LL / 256, BATCH), 192>>>(b_proj, out);
}